// round 5
// baseline (speedup 1.0000x reference)
#include <cuda_runtime.h>
#include <cstdint>
#include <cstddef>

#define BATCH 4
#define NQ    2048
#define NK    2048
#define EMB   512
#define NH    8
#define HD    64
#define NTOK  (BATCH * NQ)
#define BHN   (BATCH * NH)
#define SCALE 0.125f

// ---------------- device-global scratch --------------------------------------
__device__ float g_qn [NTOK * EMB];
__device__ float g_kvn[NTOK * EMB];
__device__ float g_q  [NTOK * EMB];
__device__ float g_k  [NTOK * EMB];
__device__ float g_v  [NTOK * EMB];
__device__ float g_ctx[NTOK * EMB];
__device__ float g_wt [4 * EMB * EMB];
__device__ unsigned char g_kvm[BATCH * NK];
__device__ unsigned long long g_mbits[(size_t)BATCH * NQ * (NK / 64)];
__device__ int g_is_byte[2];

// ---------------- helpers -----------------------------------------------------
__device__ __forceinline__ float tf32r(float x) {
    uint32_t u;
    asm("cvt.rna.tf32.f32 %0, %1;" : "=r"(u) : "f"(x));
    return __uint_as_float(u);
}

#define MMA_TF32(C, A, B) \
    asm volatile( \
        "mma.sync.aligned.m16n8k8.row.col.f32.tf32.tf32.f32 " \
        "{%0,%1,%2,%3}, {%4,%5,%6,%7}, {%8,%9}, {%0,%1,%2,%3};" \
        : "+f"((C)[0]), "+f"((C)[1]), "+f"((C)[2]), "+f"((C)[3]) \
        : "r"((A)[0]), "r"((A)[1]), "r"((A)[2]), "r"((A)[3]), \
          "r"((B)[0]), "r"((B)[1]))

// ---------------- core tf32 GEMM (projections) --------------------------------
template<int NT, int NC>
__device__ __forceinline__ void gemm_core(
        const float* __restrict__ A, size_t lda,
        const float* __restrict__ B, size_t ldb,
        float* __restrict__ C, size_t ldc,
        const float* __restrict__ bias) {
    extern __shared__ float smf[];
    float (*As)[36] = (float(*)[36])smf;
    float (*Bs)[36] = (float(*)[36])(smf + 128 * 36);

    const int tid  = threadIdx.x;
    const int lane = tid & 31, wid = tid >> 5;
    const int wm = wid & 3, wn = wid >> 2;
    const int g = lane >> 2, t = lane & 3;
    constexpr int NTW = NT / 16;
    constexpr int NBF = NT / 32;

    float c[2][NTW][4];
    #pragma unroll
    for (int mt = 0; mt < 2; mt++)
        #pragma unroll
        for (int nt = 0; nt < NTW; nt++)
            #pragma unroll
            for (int j = 0; j < 4; j++) c[mt][nt][j] = 0.0f;

    float4 pa[4], pb[NBF];
    #pragma unroll
    for (int i = 0; i < 4; i++) {
        int s = tid + i * 256, r = s >> 3, f = s & 7;
        pa[i] = *(const float4*)(A + (size_t)r * lda + f * 4);
    }
    #pragma unroll
    for (int i = 0; i < NBF; i++) {
        int s = tid + i * 256, r = s >> 3, f = s & 7;
        pb[i] = *(const float4*)(B + (size_t)r * ldb + f * 4);
    }

    for (int ch = 0; ch < NC; ch++) {
        #pragma unroll
        for (int i = 0; i < 4; i++) {
            int s = tid + i * 256, r = s >> 3, f = s & 7;
            float4 v = pa[i];
            v.x = tf32r(v.x); v.y = tf32r(v.y);
            v.z = tf32r(v.z); v.w = tf32r(v.w);
            *(float4*)&As[r][f * 4] = v;
        }
        #pragma unroll
        for (int i = 0; i < NBF; i++) {
            int s = tid + i * 256, r = s >> 3, f = s & 7;
            float4 v = pb[i];
            v.x = tf32r(v.x); v.y = tf32r(v.y);
            v.z = tf32r(v.z); v.w = tf32r(v.w);
            *(float4*)&Bs[r][f * 4] = v;
        }
        __syncthreads();

        if (ch + 1 < NC) {
            int co = (ch + 1) * 32;
            #pragma unroll
            for (int i = 0; i < 4; i++) {
                int s = tid + i * 256, r = s >> 3, f = s & 7;
                pa[i] = *(const float4*)(A + (size_t)r * lda + co + f * 4);
            }
            #pragma unroll
            for (int i = 0; i < NBF; i++) {
                int s = tid + i * 256, r = s >> 3, f = s & 7;
                pb[i] = *(const float4*)(B + (size_t)r * ldb + co + f * 4);
            }
        }

        #pragma unroll
        for (int ks = 0; ks < 4; ks++) {
            int k = ks * 8;
            uint32_t a[2][4];
            #pragma unroll
            for (int mt = 0; mt < 2; mt++) {
                int r = wm * 32 + mt * 16 + g;
                a[mt][0] = __float_as_uint(As[r][k + t]);
                a[mt][1] = __float_as_uint(As[r + 8][k + t]);
                a[mt][2] = __float_as_uint(As[r][k + t + 4]);
                a[mt][3] = __float_as_uint(As[r + 8][k + t + 4]);
            }
            uint32_t b[NTW][2];
            #pragma unroll
            for (int nt = 0; nt < NTW; nt++) {
                int n = wn * (NT / 2) + nt * 8 + g;
                b[nt][0] = __float_as_uint(Bs[n][k + t]);
                b[nt][1] = __float_as_uint(Bs[n][k + t + 4]);
            }
            #pragma unroll
            for (int mt = 0; mt < 2; mt++)
                #pragma unroll
                for (int nt = 0; nt < NTW; nt++)
                    MMA_TF32(c[mt][nt], a[mt], b[nt]);
        }
        __syncthreads();
    }

    #pragma unroll
    for (int mt = 0; mt < 2; mt++) {
        #pragma unroll
        for (int nt = 0; nt < NTW; nt++) {
            int m   = wm * 32 + mt * 16 + g;
            int col = wn * (NT / 2) + nt * 8 + t * 2;
            float bx = 0.0f, by = 0.0f;
            if (bias) { bx = bias[col]; by = bias[col + 1]; }
            *(float2*)(C + (size_t)m * ldc + col) =
                make_float2(c[mt][nt][0] + bx, c[mt][nt][1] + by);
            *(float2*)(C + (size_t)(m + 8) * ldc + col) =
                make_float2(c[mt][nt][2] + bx, c[mt][nt][3] + by);
        }
    }
}

__global__ void __launch_bounds__(256) proj_kernel(
        const float* __restrict__ X, const float* __restrict__ Wt,
        const float* __restrict__ bias, float* __restrict__ Y) {
    size_t bm = (size_t)blockIdx.y * 128, bn = (size_t)blockIdx.x * 128;
    gemm_core<128, 16>(X + bm * EMB, EMB, Wt + bn * EMB, EMB,
                       Y + bm * EMB + bn, EMB, bias + bn);
}

// ---------------- fused flash attention (tf32 MMA) ----------------------------
// Block: (qt, bh). 256 threads = 8 warps; warp w owns q-rows [w*16, w*16+16).
__global__ void __launch_bounds__(256) fattn_kernel(
        const float* __restrict__ Qp, const float* __restrict__ Kp,
        const float* __restrict__ Vp,
        const unsigned long long* __restrict__ mbits,
        float* __restrict__ ctx) {
    extern __shared__ float smf[];
    float (*Ks)[68]  = (float(*)[68])smf;              // [64 keys][64 d]
    float (*Vst)[68] = (float(*)[68])(smf + 64 * 68);  // [64 d][64 keys]
    float (*Ps)[68]  = (float(*)[68])(smf + 2 * 64 * 68); // [128 rows][64 keys]

    const int tid  = threadIdx.x;
    const int lane = tid & 31, w = tid >> 5;
    const int g = lane >> 2, t = lane & 3;
    const int qt = blockIdx.x, bh = blockIdx.y;
    const int b = bh >> 3, h = bh & 7;
    const int row0 = w * 16 + g, row1 = row0 + 8;      // block-local q rows

    // Q -> registers (scaled + tf32), A-fragment layout per k-step
    uint32_t qa[8][4];
    {
        const float* q0 = Qp + (size_t)(b * NQ + qt * 128 + row0) * EMB + h * HD;
        const float* q1 = Qp + (size_t)(b * NQ + qt * 128 + row1) * EMB + h * HD;
        #pragma unroll
        for (int ks = 0; ks < 8; ks++) {
            qa[ks][0] = __float_as_uint(tf32r(q0[ks * 8 + t] * SCALE));
            qa[ks][1] = __float_as_uint(tf32r(q1[ks * 8 + t] * SCALE));
            qa[ks][2] = __float_as_uint(tf32r(q0[ks * 8 + t + 4] * SCALE));
            qa[ks][3] = __float_as_uint(tf32r(q1[ks * 8 + t + 4] * SCALE));
        }
    }

    float m0 = -1e30f, m1 = -1e30f, l0 = 0.0f, l1 = 0.0f;
    float acc[8][4];
    #pragma unroll
    for (int nt = 0; nt < 8; nt++)
        #pragma unroll
        for (int j = 0; j < 4; j++) acc[nt][j] = 0.0f;

    const unsigned long long* mb0 =
        mbits + ((size_t)b * NQ + qt * 128 + row0) * (NK / 64);
    const unsigned long long* mb1 =
        mbits + ((size_t)b * NQ + qt * 128 + row1) * (NK / 64);

    for (int kt = 0; kt < NK / 64; kt++) {
        int k0 = kt * 64;
        __syncthreads();
        // stage K [key][d] and V^T [d][key]
        #pragma unroll
        for (int i = 0; i < 4; i++) {
            int s = tid + i * 256;
            int key = s >> 4, f = s & 15;
            size_t base = (size_t)(b * NK + k0 + key) * EMB + h * HD + f * 4;
            float4 kv = *(const float4*)(Kp + base);
            kv.x = tf32r(kv.x); kv.y = tf32r(kv.y);
            kv.z = tf32r(kv.z); kv.w = tf32r(kv.w);
            *(float4*)&Ks[key][f * 4] = kv;
            float4 vv = *(const float4*)(Vp + base);
            Vst[f * 4 + 0][key] = tf32r(vv.x);
            Vst[f * 4 + 1][key] = tf32r(vv.y);
            Vst[f * 4 + 2][key] = tf32r(vv.z);
            Vst[f * 4 + 3][key] = tf32r(vv.w);
        }
        __syncthreads();

        // S = (Q*scale) @ K^T
        float sc[8][4];
        #pragma unroll
        for (int nt = 0; nt < 8; nt++)
            #pragma unroll
            for (int j = 0; j < 4; j++) sc[nt][j] = 0.0f;
        #pragma unroll
        for (int ks = 0; ks < 8; ks++) {
            int k = ks * 8;
            uint32_t bf[8][2];
            #pragma unroll
            for (int nt = 0; nt < 8; nt++) {
                int n = nt * 8 + g;
                bf[nt][0] = __float_as_uint(Ks[n][k + t]);
                bf[nt][1] = __float_as_uint(Ks[n][k + t + 4]);
            }
            #pragma unroll
            for (int nt = 0; nt < 8; nt++)
                MMA_TF32(sc[nt], qa[ks], bf[nt]);
        }

        // mask + tile max
        unsigned long long w0 = mb0[kt], w1 = mb1[kt];
        float tm0 = -1e30f, tm1 = -1e30f;
        #pragma unroll
        for (int nt = 0; nt < 8; nt++) {
            int c0 = nt * 8 + t * 2;
            sc[nt][0] = ((w0 >> c0) & 1)       ? sc[nt][0] : -1e30f;
            sc[nt][1] = ((w0 >> (c0 + 1)) & 1) ? sc[nt][1] : -1e30f;
            sc[nt][2] = ((w1 >> c0) & 1)       ? sc[nt][2] : -1e30f;
            sc[nt][3] = ((w1 >> (c0 + 1)) & 1) ? sc[nt][3] : -1e30f;
            tm0 = fmaxf(tm0, fmaxf(sc[nt][0], sc[nt][1]));
            tm1 = fmaxf(tm1, fmaxf(sc[nt][2], sc[nt][3]));
        }
        tm0 = fmaxf(tm0, __shfl_xor_sync(0xffffffffu, tm0, 1));
        tm0 = fmaxf(tm0, __shfl_xor_sync(0xffffffffu, tm0, 2));
        tm1 = fmaxf(tm1, __shfl_xor_sync(0xffffffffu, tm1, 1));
        tm1 = fmaxf(tm1, __shfl_xor_sync(0xffffffffu, tm1, 2));

        float mn0 = fmaxf(m0, tm0), mn1 = fmaxf(m1, tm1);
        float corr0 = __expf(m0 - mn0), corr1 = __expf(m1 - mn1);

        __syncwarp();                       // prev PV reads of Ps done
        float ps0 = 0.0f, ps1 = 0.0f;
        #pragma unroll
        for (int nt = 0; nt < 8; nt++) {
            int c0 = nt * 8 + t * 2;
            float p00 = ((w0 >> c0) & 1)       ? __expf(sc[nt][0] - mn0) : 0.0f;
            float p01 = ((w0 >> (c0 + 1)) & 1) ? __expf(sc[nt][1] - mn0) : 0.0f;
            float p10 = ((w1 >> c0) & 1)       ? __expf(sc[nt][2] - mn1) : 0.0f;
            float p11 = ((w1 >> (c0 + 1)) & 1) ? __expf(sc[nt][3] - mn1) : 0.0f;
            ps0 += p00 + p01;
            ps1 += p10 + p11;
            *(float2*)&Ps[row0][c0] = make_float2(tf32r(p00), tf32r(p01));
            *(float2*)&Ps[row1][c0] = make_float2(tf32r(p10), tf32r(p11));
        }
        ps0 += __shfl_xor_sync(0xffffffffu, ps0, 1);
        ps0 += __shfl_xor_sync(0xffffffffu, ps0, 2);
        ps1 += __shfl_xor_sync(0xffffffffu, ps1, 1);
        ps1 += __shfl_xor_sync(0xffffffffu, ps1, 2);
        l0 = l0 * corr0 + ps0;  m0 = mn0;
        l1 = l1 * corr1 + ps1;  m1 = mn1;
        #pragma unroll
        for (int nt = 0; nt < 8; nt++) {
            acc[nt][0] *= corr0; acc[nt][1] *= corr0;
            acc[nt][2] *= corr1; acc[nt][3] *= corr1;
        }
        __syncwarp();                       // Ps visible to warp

        // O += P @ V
        #pragma unroll
        for (int ks = 0; ks < 8; ks++) {
            int k = ks * 8;
            uint32_t pa[4];
            pa[0] = __float_as_uint(Ps[row0][k + t]);
            pa[1] = __float_as_uint(Ps[row1][k + t]);
            pa[2] = __float_as_uint(Ps[row0][k + t + 4]);
            pa[3] = __float_as_uint(Ps[row1][k + t + 4]);
            uint32_t bv[8][2];
            #pragma unroll
            for (int nt = 0; nt < 8; nt++) {
                int n = nt * 8 + g;
                bv[nt][0] = __float_as_uint(Vst[n][k + t]);
                bv[nt][1] = __float_as_uint(Vst[n][k + t + 4]);
            }
            #pragma unroll
            for (int nt = 0; nt < 8; nt++)
                MMA_TF32(acc[nt], pa, bv[nt]);
        }
    }

    float inv0 = (l0 > 0.0f) ? (1.0f / l0) : 0.0f;
    float inv1 = (l1 > 0.0f) ? (1.0f / l1) : 0.0f;
    float* o0 = ctx + (size_t)(b * NQ + qt * 128 + row0) * EMB + h * HD;
    float* o1 = ctx + (size_t)(b * NQ + qt * 128 + row1) * EMB + h * HD;
    #pragma unroll
    for (int nt = 0; nt < 8; nt++) {
        int c0 = nt * 8 + t * 2;
        *(float2*)(o0 + c0) = make_float2(acc[nt][0] * inv0, acc[nt][1] * inv0);
        *(float2*)(o1 + c0) = make_float2(acc[nt][2] * inv1, acc[nt][3] * inv1);
    }
}

// ---------------- masks -------------------------------------------------------
__global__ void detect_mask_kernel(const unsigned char* kvm_raw,
                                   const unsigned char* spm_raw) {
    __shared__ int found[2];
    if (threadIdx.x == 0) { found[0] = 0; found[1] = 0; }
    __syncthreads();
    for (int i = threadIdx.x; i < 8192; i += blockDim.x) {
        if ((i & 3) != 0) {
            if (kvm_raw[i]) atomicOr(&found[0], 1);
            if (spm_raw[i]) atomicOr(&found[1], 1);
        }
    }
    __syncthreads();
    if (threadIdx.x == 0) { g_is_byte[0] = found[0]; g_is_byte[1] = found[1]; }
}
__global__ void expand_kv_kernel(const void* raw) {
    int i = blockIdx.x * blockDim.x + threadIdx.x;
    if (i < BATCH * NK)
        g_kvm[i] = g_is_byte[0] ? (((const unsigned char*)raw)[i] != 0)
                                : (((const int*)raw)[i] != 0);
}
// combined (kvm & spm) -> 1 bit per key; word idx = (b*NQ+q)*32 + k/64
__global__ void mask_bits_kernel(const void* raw) {
    int idx = blockIdx.x * blockDim.x + threadIdx.x;   // 262144 words
    int bq = idx >> 5, wk = idx & 31;
    int b = bq >> 11;
    int kbase = wk * 64;
    const unsigned char* kv = g_kvm + b * NK + kbase;
    unsigned long long bits = 0;
    if (g_is_byte[1]) {
        const unsigned char* sp = (const unsigned char*)raw + (size_t)bq * NK + kbase;
        #pragma unroll 8
        for (int j = 0; j < 64; j++)
            if (sp[j] && kv[j]) bits |= 1ULL << j;
    } else {
        const int* sp = (const int*)raw + (size_t)bq * NK + kbase;
        #pragma unroll 8
        for (int j = 0; j < 64; j++)
            if (sp[j] && kv[j]) bits |= 1ULL << j;
    }
    g_mbits[idx] = bits;
}

// ---------------- LayerNorm ---------------------------------------------------
__global__ void lnorm_kernel(const float* __restrict__ x,
                             const float* __restrict__ g,
                             const float* __restrict__ b,
                             float* __restrict__ y) {
    __shared__ float red[8];
    int row = blockIdx.x, t = threadIdx.x;
    float4 v = ((const float4*)(x + (size_t)row * EMB))[t];
    float s  = v.x + v.y + v.z + v.w;
    float s2 = v.x*v.x + v.y*v.y + v.z*v.z + v.w*v.w;
    #pragma unroll
    for (int o = 16; o > 0; o >>= 1) {
        s  += __shfl_xor_sync(0xffffffffu, s,  o);
        s2 += __shfl_xor_sync(0xffffffffu, s2, o);
    }
    if ((t & 31) == 0) { red[t >> 5] = s; red[4 + (t >> 5)] = s2; }
    __syncthreads();
    float tot  = red[0] + red[1] + red[2] + red[3];
    float tot2 = red[4] + red[5] + red[6] + red[7];
    float mu  = tot * (1.0f / EMB);
    float var = tot2 * (1.0f / EMB) - mu * mu;
    float inv = rsqrtf(var + 1e-5f);
    float4 gg = ((const float4*)g)[t];
    float4 bb = ((const float4*)b)[t];
    float4 o;
    o.x = (v.x - mu) * inv * gg.x + bb.x;
    o.y = (v.y - mu) * inv * gg.y + bb.y;
    o.z = (v.z - mu) * inv * gg.z + bb.z;
    o.w = (v.w - mu) * inv * gg.w + bb.w;
    ((float4*)(y + (size_t)row * EMB))[t] = o;
}

// ---------------- weight transpose --------------------------------------------
__global__ void wt_kernel(const float* __restrict__ W, float* __restrict__ Wt) {
    __shared__ float tile[32][33];
    int bx = blockIdx.x * 32, by = blockIdx.y * 32;
    int tx = threadIdx.x, ty = threadIdx.y;
    #pragma unroll
    for (int i = 0; i < 4; i++)
        tile[ty + i * 8][tx] = W[(size_t)(by + ty + i * 8) * EMB + bx + tx];
    __syncthreads();
    #pragma unroll
    for (int i = 0; i < 4; i++)
        Wt[(size_t)(bx + ty + i * 8) * EMB + by + tx] = tile[tx][ty + i * 8];
}

// ---------------- launch ------------------------------------------------------
extern "C" void kernel_launch(void* const* d_in, const int* in_sizes, int n_in,
                              void* d_out, int out_size) {
    const float* query     = (const float*)d_in[0];
    const float* key_value = (const float*)d_in[1];
    const void*  kvm_raw   = d_in[2];
    const void*  spm_raw   = d_in[3];
    const float* ln_q_g  = (const float*)d_in[4];
    const float* ln_q_b  = (const float*)d_in[5];
    const float* ln_kv_g = (const float*)d_in[6];
    const float* ln_kv_b = (const float*)d_in[7];
    const float* Wq = (const float*)d_in[8];
    const float* bq = (const float*)d_in[9];
    const float* Wk = (const float*)d_in[10];
    const float* bk = (const float*)d_in[11];
    const float* Wv = (const float*)d_in[12];
    const float* bv = (const float*)d_in[13];
    const float* Wo = (const float*)d_in[14];
    const float* bo = (const float*)d_in[15];
    float* out = (float*)d_out;

    void *p_qn, *p_kvn, *p_q, *p_k, *p_v, *p_ctx, *p_wt, *p_mb;
    cudaGetSymbolAddress(&p_qn,  g_qn);
    cudaGetSymbolAddress(&p_kvn, g_kvn);
    cudaGetSymbolAddress(&p_q,   g_q);
    cudaGetSymbolAddress(&p_k,   g_k);
    cudaGetSymbolAddress(&p_v,   g_v);
    cudaGetSymbolAddress(&p_ctx, g_ctx);
    cudaGetSymbolAddress(&p_wt,  g_wt);
    cudaGetSymbolAddress(&p_mb,  g_mbits);
    float* wt = (float*)p_wt;

    detect_mask_kernel<<<1, 256>>>((const unsigned char*)kvm_raw,
                                   (const unsigned char*)spm_raw);
    expand_kv_kernel<<<(BATCH * NK + 255) / 256, 256>>>(kvm_raw);
    mask_bits_kernel<<<(BATCH * NQ * (NK / 64)) / 256, 256>>>(spm_raw);

    lnorm_kernel<<<NTOK, 128>>>(query,     ln_q_g,  ln_q_b,  (float*)p_qn);
    lnorm_kernel<<<NTOK, 128>>>(key_value, ln_kv_g, ln_kv_b, (float*)p_kvn);

    dim3 tb(32, 8), tg(16, 16);
    wt_kernel<<<tg, tb>>>(Wq, wt + 0 * EMB * EMB);
    wt_kernel<<<tg, tb>>>(Wk, wt + 1 * EMB * EMB);
    wt_kernel<<<tg, tb>>>(Wv, wt + 2 * EMB * EMB);
    wt_kernel<<<tg, tb>>>(Wo, wt + 3 * EMB * EMB);

    const int SMEM128 = (128 + 128) * 36 * 4;
    dim3 pg(EMB / 128, NTOK / 128);
    proj_kernel<<<pg, 256, SMEM128>>>((const float*)p_qn,
        wt + 0 * EMB * EMB, bq, (float*)p_q);
    proj_kernel<<<pg, 256, SMEM128>>>((const float*)p_kvn,
        wt + 1 * EMB * EMB, bk, (float*)p_k);
    proj_kernel<<<pg, 256, SMEM128>>>((const float*)p_kvn,
        wt + 2 * EMB * EMB, bv, (float*)p_v);

    const int SMEMF = 256 * 68 * 4;   // 69632
    cudaFuncSetAttribute(fattn_kernel,
        cudaFuncAttributeMaxDynamicSharedMemorySize, SMEMF);
    dim3 fg(NQ / 128, BHN);
    fattn_kernel<<<fg, 256, SMEMF>>>((const float*)p_q, (const float*)p_k,
        (const float*)p_v, (const unsigned long long*)p_mb, (float*)p_ctx);

    proj_kernel<<<pg, 256, SMEM128>>>((const float*)p_ctx,
        wt + 3 * EMB * EMB, bo, out);
}

// round 6
// speedup vs baseline: 1.8851x; 1.8851x over previous
#include <cuda_runtime.h>
#include <cuda_fp16.h>
#include <cstdint>
#include <cstddef>

#define BATCH 4
#define NQ    2048
#define NK    2048
#define EMB   512
#define NH    8
#define HD    64
#define NTOK  (BATCH * NQ)
#define BHN   (BATCH * NH)

// ---------------- device-global scratch (halves) ------------------------------
__device__ __half g_qn [NTOK * EMB];
__device__ __half g_kvn[NTOK * EMB];
__device__ __half g_q  [NTOK * EMB];          // pre-scaled by 0.125
__device__ __half g_k  [NTOK * EMB];
__device__ __half g_vt [BHN * HD * NK];       // V^T per (b,h): [d][key]
__device__ __half g_ctx[NTOK * EMB];
__device__ __half g_wt [4 * EMB * EMB];       // W^T, k-major rows
__device__ unsigned long long g_mbits[(size_t)BATCH * NQ * (NK / 64)];
__device__ int g_is_byte[2];

// ---------------- fp16 MMA ----------------------------------------------------
#define MMA_F16(C, A, B) \
    asm volatile( \
        "mma.sync.aligned.m16n8k16.row.col.f32.f16.f16.f32 " \
        "{%0,%1,%2,%3}, {%4,%5,%6,%7}, {%8,%9}, {%0,%1,%2,%3};" \
        : "+f"((C)[0]), "+f"((C)[1]), "+f"((C)[2]), "+f"((C)[3]) \
        : "r"((A)[0]), "r"((A)[1]), "r"((A)[2]), "r"((A)[3]), \
          "r"((B)[0]), "r"((B)[1]))

// ---------------- fp16 GEMM mainloop: C[128x128] = A[128,512] @ B[128,512]^T ---
// 256 threads, 8 warps (4M x 2N); warp tile 32x64; BK=32 (2 k16 steps/chunk).
__device__ __forceinline__ void gemm16_mainloop(
        const __half* __restrict__ A, const __half* __restrict__ B,
        float (&c)[2][8][4]) {
    __shared__ __half As[128][40];
    __shared__ __half Bs[128][40];
    const int tid = threadIdx.x;
    const int lane = tid & 31, wid = tid >> 5;
    const int wm = wid & 3, wn = wid >> 2;
    const int g = lane >> 2, t = lane & 3;

    #pragma unroll
    for (int mt = 0; mt < 2; mt++)
        #pragma unroll
        for (int nt = 0; nt < 8; nt++)
            #pragma unroll
            for (int j = 0; j < 4; j++) c[mt][nt][j] = 0.0f;

    uint4 pa[2], pb[2];
    #pragma unroll
    for (int i = 0; i < 2; i++) {
        int s = tid + i * 256, r = s >> 2, f = s & 3;
        pa[i] = *(const uint4*)(A + (size_t)r * EMB + f * 8);
        pb[i] = *(const uint4*)(B + (size_t)r * EMB + f * 8);
    }

    for (int ch = 0; ch < 16; ch++) {
        #pragma unroll
        for (int i = 0; i < 2; i++) {
            int s = tid + i * 256, r = s >> 2, f = s & 3;
            *(uint4*)&As[r][f * 8] = pa[i];
            *(uint4*)&Bs[r][f * 8] = pb[i];
        }
        __syncthreads();
        if (ch + 1 < 16) {
            int co = (ch + 1) * 32;
            #pragma unroll
            for (int i = 0; i < 2; i++) {
                int s = tid + i * 256, r = s >> 2, f = s & 3;
                pa[i] = *(const uint4*)(A + (size_t)r * EMB + co + f * 8);
                pb[i] = *(const uint4*)(B + (size_t)r * EMB + co + f * 8);
            }
        }
        #pragma unroll
        for (int ks = 0; ks < 2; ks++) {
            int k = ks * 16;
            uint32_t a[2][4];
            #pragma unroll
            for (int mt = 0; mt < 2; mt++) {
                int r = wm * 32 + mt * 16 + g;
                a[mt][0] = *(const uint32_t*)&As[r][k + 2 * t];
                a[mt][1] = *(const uint32_t*)&As[r + 8][k + 2 * t];
                a[mt][2] = *(const uint32_t*)&As[r][k + 2 * t + 8];
                a[mt][3] = *(const uint32_t*)&As[r + 8][k + 2 * t + 8];
            }
            uint32_t b[8][2];
            #pragma unroll
            for (int nt = 0; nt < 8; nt++) {
                int n = wn * 64 + nt * 8 + g;
                b[nt][0] = *(const uint32_t*)&Bs[n][k + 2 * t];
                b[nt][1] = *(const uint32_t*)&Bs[n][k + 2 * t + 8];
            }
            #pragma unroll
            for (int mt = 0; mt < 2; mt++)
                #pragma unroll
                for (int nt = 0; nt < 8; nt++)
                    MMA_F16(c[mt][nt], a[mt], b[nt]);
        }
        __syncthreads();
    }
}

// Q/K/V projections in one launch. z=0: Q (scaled 0.125), z=1: K, z=2: V^T.
__global__ void __launch_bounds__(256, 2) proj_qkv_kernel(
        const __half* __restrict__ qn, const __half* __restrict__ kvn,
        const __half* __restrict__ wt,
        const float* __restrict__ bq, const float* __restrict__ bk,
        const float* __restrict__ bv,
        __half* __restrict__ q, __half* __restrict__ k,
        __half* __restrict__ vt) {
    const int z = blockIdx.z;
    const size_t bm = (size_t)blockIdx.y * 128, bn = (size_t)blockIdx.x * 128;
    const __half* A = (z == 0 ? qn : kvn) + bm * EMB;
    const __half* B = wt + (size_t)z * EMB * EMB + bn * EMB;
    float c[2][8][4];
    gemm16_mainloop(A, B, c);

    const int tid = threadIdx.x, lane = tid & 31, wid = tid >> 5;
    const int wm = wid & 3, wn = wid >> 2, g = lane >> 2, t = lane & 3;
    const float* bias = (z == 0) ? bq : (z == 1) ? bk : bv;
    const float scale = (z == 0) ? 0.125f : 1.0f;

    #pragma unroll
    for (int mt = 0; mt < 2; mt++) {
        #pragma unroll
        for (int nt = 0; nt < 8; nt++) {
            int m   = (int)bm + wm * 32 + mt * 16 + g;
            int col = (int)bn + wn * 64 + nt * 8 + 2 * t;
            float b0 = bias[col], b1 = bias[col + 1];
            float v0 = (c[mt][nt][0] + b0) * scale;
            float v1 = (c[mt][nt][1] + b1) * scale;
            float v2 = (c[mt][nt][2] + b0) * scale;
            float v3 = (c[mt][nt][3] + b1) * scale;
            if (z < 2) {
                __half* dst = (z == 0) ? q : k;
                *(half2*)(dst + (size_t)m * EMB + col) = __floats2half2_rn(v0, v1);
                *(half2*)(dst + (size_t)(m + 8) * EMB + col) = __floats2half2_rn(v2, v3);
            } else {
                int h = col >> 6, d = col & 63;
                int b_ = m >> 11;
                size_t base = ((size_t)(b_ * NH + h) * HD);
                int tok = m & 2047;
                vt[(base + d) * NK + tok]           = __float2half_rn(v0);
                vt[(base + d + 1) * NK + tok]       = __float2half_rn(v1);
                vt[(base + d) * NK + tok + 8]       = __float2half_rn(v2);
                vt[(base + d + 1) * NK + tok + 8]   = __float2half_rn(v3);
            }
        }
    }
}

// Output projection: fp32 result + bias into d_out.
__global__ void __launch_bounds__(256, 2) proj_o_kernel(
        const __half* __restrict__ ctx, const __half* __restrict__ wt,
        const float* __restrict__ bo, float* __restrict__ out) {
    const size_t bm = (size_t)blockIdx.y * 128, bn = (size_t)blockIdx.x * 128;
    float c[2][8][4];
    gemm16_mainloop(ctx + bm * EMB, wt + 3ull * EMB * EMB + bn * EMB, c);

    const int tid = threadIdx.x, lane = tid & 31, wid = tid >> 5;
    const int wm = wid & 3, wn = wid >> 2, g = lane >> 2, t = lane & 3;
    #pragma unroll
    for (int mt = 0; mt < 2; mt++) {
        #pragma unroll
        for (int nt = 0; nt < 8; nt++) {
            int m   = (int)bm + wm * 32 + mt * 16 + g;
            int col = (int)bn + wn * 64 + nt * 8 + 2 * t;
            float b0 = bo[col], b1 = bo[col + 1];
            *(float2*)(out + (size_t)m * EMB + col) =
                make_float2(c[mt][nt][0] + b0, c[mt][nt][1] + b1);
            *(float2*)(out + (size_t)(m + 8) * EMB + col) =
                make_float2(c[mt][nt][2] + b0, c[mt][nt][3] + b1);
        }
    }
}

// ---------------- fused flash attention (fp16 MMA) ----------------------------
// Block (qt, bh): 256 threads, 8 warps; warp w owns q-rows [w*16, w*16+16).
__global__ void __launch_bounds__(256, 2) fattn_kernel(
        const __half* __restrict__ Qp, const __half* __restrict__ Kp,
        const __half* __restrict__ Vtp,
        const unsigned long long* __restrict__ mbits,
        __half* __restrict__ ctx) {
    __shared__ __half Ks [64][72];    // [key][d]
    __shared__ __half Vst[64][72];    // [d][key]
    __shared__ __half Ps [128][72];   // [qrow][key]

    const int tid = threadIdx.x;
    const int lane = tid & 31, w = tid >> 5;
    const int g = lane >> 2, t = lane & 3;
    const int qt = blockIdx.x, bh = blockIdx.y;
    const int b = bh >> 3, h = bh & 7;
    const int row0 = w * 16 + g, row1 = row0 + 8;

    // Q fragments (already scaled by 0.125 and rounded to fp16)
    uint32_t qa[4][4];
    {
        const __half* q0 = Qp + (size_t)(b * NQ + qt * 128 + row0) * EMB + h * HD;
        const __half* q1 = Qp + (size_t)(b * NQ + qt * 128 + row1) * EMB + h * HD;
        #pragma unroll
        for (int ks = 0; ks < 4; ks++) {
            qa[ks][0] = *(const uint32_t*)(q0 + ks * 16 + 2 * t);
            qa[ks][1] = *(const uint32_t*)(q1 + ks * 16 + 2 * t);
            qa[ks][2] = *(const uint32_t*)(q0 + ks * 16 + 2 * t + 8);
            qa[ks][3] = *(const uint32_t*)(q1 + ks * 16 + 2 * t + 8);
        }
    }

    float m0 = -1e30f, m1 = -1e30f, l0 = 0.0f, l1 = 0.0f;
    float acc[8][4];
    #pragma unroll
    for (int nt = 0; nt < 8; nt++)
        #pragma unroll
        for (int j = 0; j < 4; j++) acc[nt][j] = 0.0f;

    const unsigned long long* mb0 =
        mbits + ((size_t)b * NQ + qt * 128 + row0) * (NK / 64);
    const unsigned long long* mb1 =
        mbits + ((size_t)b * NQ + qt * 128 + row1) * (NK / 64);

    const __half* Kbase  = Kp + ((size_t)b * NK) * EMB + h * HD;
    const __half* Vtbase = Vtp + (size_t)bh * HD * NK;

    for (int kt = 0; kt < NK / 64; kt++) {
        int k0 = kt * 64;
        __syncthreads();
        // stage K [key][d] and V^T [d][key] — both straight aligned copies
        #pragma unroll
        for (int i = 0; i < 2; i++) {
            int s = tid + i * 256;
            int r = s >> 3, f = s & 7;
            *(uint4*)&Ks[r][f * 8] =
                *(const uint4*)(Kbase + (size_t)(k0 + r) * EMB + f * 8);
            *(uint4*)&Vst[r][f * 8] =
                *(const uint4*)(Vtbase + (size_t)r * NK + k0 + f * 8);
        }
        __syncthreads();

        // S = Q @ K^T
        float sc[8][4];
        #pragma unroll
        for (int nt = 0; nt < 8; nt++)
            #pragma unroll
            for (int j = 0; j < 4; j++) sc[nt][j] = 0.0f;
        #pragma unroll
        for (int ks = 0; ks < 4; ks++) {
            int k = ks * 16;
            uint32_t bf[8][2];
            #pragma unroll
            for (int nt = 0; nt < 8; nt++) {
                int n = nt * 8 + g;
                bf[nt][0] = *(const uint32_t*)&Ks[n][k + 2 * t];
                bf[nt][1] = *(const uint32_t*)&Ks[n][k + 2 * t + 8];
            }
            #pragma unroll
            for (int nt = 0; nt < 8; nt++)
                MMA_F16(sc[nt], qa[ks], bf[nt]);
        }

        // mask + tile max
        unsigned long long w0 = mb0[kt], w1 = mb1[kt];
        float tm0 = -1e30f, tm1 = -1e30f;
        #pragma unroll
        for (int nt = 0; nt < 8; nt++) {
            int c0 = nt * 8 + 2 * t;
            sc[nt][0] = ((w0 >> c0) & 1)       ? sc[nt][0] : -1e30f;
            sc[nt][1] = ((w0 >> (c0 + 1)) & 1) ? sc[nt][1] : -1e30f;
            sc[nt][2] = ((w1 >> c0) & 1)       ? sc[nt][2] : -1e30f;
            sc[nt][3] = ((w1 >> (c0 + 1)) & 1) ? sc[nt][3] : -1e30f;
            tm0 = fmaxf(tm0, fmaxf(sc[nt][0], sc[nt][1]));
            tm1 = fmaxf(tm1, fmaxf(sc[nt][2], sc[nt][3]));
        }
        tm0 = fmaxf(tm0, __shfl_xor_sync(0xffffffffu, tm0, 1));
        tm0 = fmaxf(tm0, __shfl_xor_sync(0xffffffffu, tm0, 2));
        tm1 = fmaxf(tm1, __shfl_xor_sync(0xffffffffu, tm1, 1));
        tm1 = fmaxf(tm1, __shfl_xor_sync(0xffffffffu, tm1, 2));

        float mn0 = fmaxf(m0, tm0), mn1 = fmaxf(m1, tm1);
        float corr0 = __expf(m0 - mn0), corr1 = __expf(m1 - mn1);

        __syncwarp();
        float ps0 = 0.0f, ps1 = 0.0f;
        #pragma unroll
        for (int nt = 0; nt < 8; nt++) {
            int c0 = nt * 8 + 2 * t;
            float p00 = (sc[nt][0] > -1e29f) ? __expf(sc[nt][0] - mn0) : 0.0f;
            float p01 = (sc[nt][1] > -1e29f) ? __expf(sc[nt][1] - mn0) : 0.0f;
            float p10 = (sc[nt][2] > -1e29f) ? __expf(sc[nt][2] - mn1) : 0.0f;
            float p11 = (sc[nt][3] > -1e29f) ? __expf(sc[nt][3] - mn1) : 0.0f;
            ps0 += p00 + p01;
            ps1 += p10 + p11;
            *(half2*)&Ps[row0][c0] = __floats2half2_rn(p00, p01);
            *(half2*)&Ps[row1][c0] = __floats2half2_rn(p10, p11);
        }
        ps0 += __shfl_xor_sync(0xffffffffu, ps0, 1);
        ps0 += __shfl_xor_sync(0xffffffffu, ps0, 2);
        ps1 += __shfl_xor_sync(0xffffffffu, ps1, 1);
        ps1 += __shfl_xor_sync(0xffffffffu, ps1, 2);
        l0 = l0 * corr0 + ps0;  m0 = mn0;
        l1 = l1 * corr1 + ps1;  m1 = mn1;
        #pragma unroll
        for (int nt = 0; nt < 8; nt++) {
            acc[nt][0] *= corr0; acc[nt][1] *= corr0;
            acc[nt][2] *= corr1; acc[nt][3] *= corr1;
        }
        __syncwarp();

        // O += P @ V   (B from V^T [d][key])
        #pragma unroll
        for (int ks = 0; ks < 4; ks++) {
            int k = ks * 16;
            uint32_t pa[4];
            pa[0] = *(const uint32_t*)&Ps[row0][k + 2 * t];
            pa[1] = *(const uint32_t*)&Ps[row1][k + 2 * t];
            pa[2] = *(const uint32_t*)&Ps[row0][k + 2 * t + 8];
            pa[3] = *(const uint32_t*)&Ps[row1][k + 2 * t + 8];
            uint32_t bv[8][2];
            #pragma unroll
            for (int nt = 0; nt < 8; nt++) {
                int n = nt * 8 + g;
                bv[nt][0] = *(const uint32_t*)&Vst[n][k + 2 * t];
                bv[nt][1] = *(const uint32_t*)&Vst[n][k + 2 * t + 8];
            }
            #pragma unroll
            for (int nt = 0; nt < 8; nt++)
                MMA_F16(acc[nt], pa, bv[nt]);
        }
    }

    float inv0 = (l0 > 0.0f) ? (1.0f / l0) : 0.0f;
    float inv1 = (l1 > 0.0f) ? (1.0f / l1) : 0.0f;
    __half* o0 = ctx + (size_t)(b * NQ + qt * 128 + row0) * EMB + h * HD;
    __half* o1 = ctx + (size_t)(b * NQ + qt * 128 + row1) * EMB + h * HD;
    #pragma unroll
    for (int nt = 0; nt < 8; nt++) {
        int c0 = nt * 8 + 2 * t;
        *(half2*)(o0 + c0) = __floats2half2_rn(acc[nt][0] * inv0, acc[nt][1] * inv0);
        *(half2*)(o1 + c0) = __floats2half2_rn(acc[nt][2] * inv1, acc[nt][3] * inv1);
    }
}

// ---------------- masks -------------------------------------------------------
__global__ void detect_mask_kernel(const unsigned char* kvm_raw,
                                   const unsigned char* spm_raw) {
    __shared__ int found[2];
    if (threadIdx.x == 0) { found[0] = 0; found[1] = 0; }
    __syncthreads();
    for (int i = threadIdx.x; i < 8192; i += blockDim.x) {
        if ((i & 3) != 0) {
            if (kvm_raw[i]) atomicOr(&found[0], 1);
            if (spm_raw[i]) atomicOr(&found[1], 1);
        }
    }
    __syncthreads();
    if (threadIdx.x == 0) { g_is_byte[0] = found[0]; g_is_byte[1] = found[1]; }
}

// (kvm & spm) -> 1 bit per key, straight from raw inputs
__global__ void mask_bits_kernel(const void* kvm_raw, const void* spm_raw) {
    int idx = blockIdx.x * blockDim.x + threadIdx.x;   // 262144 words
    int bq = idx >> 5, wk = idx & 31;
    int b = bq >> 11;
    int kbase = wk * 64;
    bool kb = g_is_byte[0] != 0, sb = g_is_byte[1] != 0;
    const unsigned char* kvc = (const unsigned char*)kvm_raw + b * NK + kbase;
    const int*           kvi = (const int*)kvm_raw + b * NK + kbase;
    const unsigned char* spc = (const unsigned char*)spm_raw + (size_t)bq * NK + kbase;
    const int*           spi = (const int*)spm_raw + (size_t)bq * NK + kbase;
    unsigned long long bits = 0;
    #pragma unroll 8
    for (int j = 0; j < 64; j++) {
        bool kv = kb ? (kvc[j] != 0) : (kvi[j] != 0);
        bool sp = sb ? (spc[j] != 0) : (spi[j] != 0);
        if (kv && sp) bits |= 1ULL << j;
    }
    g_mbits[idx] = bits;
}

// ---------------- LayerNorm (both tensors, half output) -----------------------
__global__ void lnorm_kernel(const float* __restrict__ xq,
                             const float* __restrict__ xkv,
                             const float* __restrict__ gq,
                             const float* __restrict__ bq,
                             const float* __restrict__ gkv,
                             const float* __restrict__ bkv,
                             __half* __restrict__ yq,
                             __half* __restrict__ ykv) {
    __shared__ float red[8];
    int row = blockIdx.x, t = threadIdx.x;
    const float* x = blockIdx.y ? xkv : xq;
    const float* g = blockIdx.y ? gkv : gq;
    const float* b = blockIdx.y ? bkv : bq;
    __half* y      = blockIdx.y ? ykv : yq;

    float4 v = ((const float4*)(x + (size_t)row * EMB))[t];
    float s  = v.x + v.y + v.z + v.w;
    float s2 = v.x*v.x + v.y*v.y + v.z*v.z + v.w*v.w;
    #pragma unroll
    for (int o = 16; o > 0; o >>= 1) {
        s  += __shfl_xor_sync(0xffffffffu, s,  o);
        s2 += __shfl_xor_sync(0xffffffffu, s2, o);
    }
    if ((t & 31) == 0) { red[t >> 5] = s; red[4 + (t >> 5)] = s2; }
    __syncthreads();
    float tot  = red[0] + red[1] + red[2] + red[3];
    float tot2 = red[4] + red[5] + red[6] + red[7];
    float mu  = tot * (1.0f / EMB);
    float var = tot2 * (1.0f / EMB) - mu * mu;
    float inv = rsqrtf(var + 1e-5f);
    float4 gg = ((const float4*)g)[t];
    float4 bb = ((const float4*)b)[t];
    float o0 = (v.x - mu) * inv * gg.x + bb.x;
    float o1 = (v.y - mu) * inv * gg.y + bb.y;
    float o2 = (v.z - mu) * inv * gg.z + bb.z;
    float o3 = (v.w - mu) * inv * gg.w + bb.w;
    __half* yr = y + (size_t)row * EMB + t * 4;
    *(half2*)(yr)     = __floats2half2_rn(o0, o1);
    *(half2*)(yr + 2) = __floats2half2_rn(o2, o3);
}

// ---------------- weight transpose (all 4, half output) -----------------------
__global__ void wt_kernel(const float* __restrict__ Wq,
                          const float* __restrict__ Wk,
                          const float* __restrict__ Wv,
                          const float* __restrict__ Wo,
                          __half* __restrict__ Wt) {
    __shared__ float tile[32][33];
    int z = blockIdx.z;
    const float* W = (z == 0) ? Wq : (z == 1) ? Wk : (z == 2) ? Wv : Wo;
    __half* dst = Wt + (size_t)z * EMB * EMB;
    int bx = blockIdx.x * 32, by = blockIdx.y * 32;
    int tx = threadIdx.x, ty = threadIdx.y;
    #pragma unroll
    for (int i = 0; i < 4; i++)
        tile[ty + i * 8][tx] = W[(size_t)(by + ty + i * 8) * EMB + bx + tx];
    __syncthreads();
    #pragma unroll
    for (int i = 0; i < 4; i++)
        dst[(size_t)(bx + ty + i * 8) * EMB + by + tx] =
            __float2half_rn(tile[tx][ty + i * 8]);
}

// ---------------- launch ------------------------------------------------------
extern "C" void kernel_launch(void* const* d_in, const int* in_sizes, int n_in,
                              void* d_out, int out_size) {
    const float* query     = (const float*)d_in[0];
    const float* key_value = (const float*)d_in[1];
    const void*  kvm_raw   = d_in[2];
    const void*  spm_raw   = d_in[3];
    const float* ln_q_g  = (const float*)d_in[4];
    const float* ln_q_b  = (const float*)d_in[5];
    const float* ln_kv_g = (const float*)d_in[6];
    const float* ln_kv_b = (const float*)d_in[7];
    const float* Wq = (const float*)d_in[8];
    const float* bq = (const float*)d_in[9];
    const float* Wk = (const float*)d_in[10];
    const float* bk = (const float*)d_in[11];
    const float* Wv = (const float*)d_in[12];
    const float* bv = (const float*)d_in[13];
    const float* Wo = (const float*)d_in[14];
    const float* bo = (const float*)d_in[15];
    float* out = (float*)d_out;

    void *p_qn, *p_kvn, *p_q, *p_k, *p_vt, *p_ctx, *p_wt, *p_mb;
    cudaGetSymbolAddress(&p_qn,  g_qn);
    cudaGetSymbolAddress(&p_kvn, g_kvn);
    cudaGetSymbolAddress(&p_q,   g_q);
    cudaGetSymbolAddress(&p_k,   g_k);
    cudaGetSymbolAddress(&p_vt,  g_vt);
    cudaGetSymbolAddress(&p_ctx, g_ctx);
    cudaGetSymbolAddress(&p_wt,  g_wt);
    cudaGetSymbolAddress(&p_mb,  g_mbits);

    // 1
    detect_mask_kernel<<<1, 256>>>((const unsigned char*)kvm_raw,
                                   (const unsigned char*)spm_raw);
    // 2
    mask_bits_kernel<<<(BATCH * NQ * (NK / 64)) / 256, 256>>>(kvm_raw, spm_raw);
    // 3
    dim3 lg(NTOK, 2);
    lnorm_kernel<<<lg, 128>>>(query, key_value, ln_q_g, ln_q_b,
                              ln_kv_g, ln_kv_b,
                              (__half*)p_qn, (__half*)p_kvn);
    // 4
    dim3 tb(32, 8), tg(16, 16, 4);
    wt_kernel<<<tg, tb>>>(Wq, Wk, Wv, Wo, (__half*)p_wt);
    // 5
    dim3 pg(EMB / 128, NTOK / 128, 3);
    proj_qkv_kernel<<<pg, 256>>>((const __half*)p_qn, (const __half*)p_kvn,
                                 (const __half*)p_wt, bq, bk, bv,
                                 (__half*)p_q, (__half*)p_k, (__half*)p_vt);
    // 6  <-- profiled launch
    dim3 fg(NQ / 128, BHN);
    fattn_kernel<<<fg, 256>>>((const __half*)p_q, (const __half*)p_k,
                              (const __half*)p_vt,
                              (const unsigned long long*)p_mb,
                              (__half*)p_ctx);
    // 7
    dim3 og(EMB / 128, NTOK / 128);
    proj_o_kernel<<<og, 256>>>((const __half*)p_ctx, (const __half*)p_wt,
                               bo, out);
}